// round 5
// baseline (speedup 1.0000x reference)
#include <cuda_runtime.h>
#include <math.h>

// Problem constants: N=50000, E=800000, F1=96, F2=64
#define MAXN 50000
#define MAXE 800000
#define F1 96
#define F2 64
#define SCAN_T 1024

// Scratch (device globals). __align__(16) for float4 access.
__device__ int g_deg[MAXN];
__device__ int g_off[MAXN + 1];
__device__ int g_cur[MAXN];
__device__ int g_srcs[MAXE];
__device__ __align__(16) float g_h [MAXN * F1];
__device__ __align__(16) float g_y2[MAXN * F2];

__device__ __forceinline__ float fcomp(const float4& v, int i) {
    return i == 0 ? v.x : i == 1 ? v.y : i == 2 ? v.z : v.w;
}

// ---------------------------------------------------------------------------
// CSR build: zero degree -> histogram -> scan -> scatter
// ---------------------------------------------------------------------------
__global__ void zero_deg_kernel(int n) {
    int i = blockIdx.x * blockDim.x + threadIdx.x;
    if (i < n) g_deg[i] = 0;
}

__global__ void hist_kernel(const int* __restrict__ dst, int e) {
    int i = blockIdx.x * blockDim.x + threadIdx.x;
    if (i < e) atomicAdd(&g_deg[dst[i]], 1);
}

// Single-block exclusive scan over n degrees -> g_off[0..n], g_cur copy.
__global__ void scan_kernel(int n) {
    __shared__ int ssum[SCAN_T];
    int t = threadIdx.x;
    int chunk = (n + SCAN_T - 1) / SCAN_T;
    int start = t * chunk;
    int end = min(start + chunk, n);
    int local = 0;
    for (int i = start; i < end; i++) local += g_deg[i];
    ssum[t] = local;
    __syncthreads();
    for (int ofs = 1; ofs < SCAN_T; ofs <<= 1) {
        int v = (t >= ofs) ? ssum[t - ofs] : 0;
        __syncthreads();
        ssum[t] += v;
        __syncthreads();
    }
    int run = ssum[t] - local;   // exclusive prefix
    for (int i = start; i < end; i++) {
        g_off[i] = run;
        g_cur[i] = run;
        run += g_deg[i];
    }
    if (t == SCAN_T - 1) g_off[n] = ssum[SCAN_T - 1];
}

__global__ void scatter_kernel(const int* __restrict__ src,
                               const int* __restrict__ dst, int e) {
    int i = blockIdx.x * blockDim.x + threadIdx.x;
    if (i < e) {
        int d = dst[i];
        int p = atomicAdd(&g_cur[d], 1);
        g_srcs[p] = src[i];
    }
}

// ---------------------------------------------------------------------------
// Layer 1 (fused CSR-aggregate + dual GEMM + ELU):
//   h = elu(x @ w1_l^T + b1 + mean_nbr(x) @ w1_r^T)
// Block (24,8)=192 thr, 32 nodes/tile, 4 feat x 4 nodes per thread.
// Aggregation: warp per dst node (lanes 0..23 own one float4 chunk each).
// ---------------------------------------------------------------------------
#define L1_TN 32
__global__ void layer1_kernel(const float* __restrict__ x,
                              const float* __restrict__ wl,
                              const float* __restrict__ bl,
                              const float* __restrict__ wr,
                              int n) {
    extern __shared__ float smem[];
    float* swl = smem;                       // [96][96]: swl[k*96+f]
    float* swr = swl + F1 * F1;
    float* sx  = swr + F1 * F1;              // [32][96] node-major
    float* sm  = sx  + L1_TN * F1;           // [32][96] neighbor-sum
    float* sb  = sm  + L1_TN * F1;           // [96]
    float* sinv= sb  + F1;                   // [32]

    const int tx = threadIdx.x;              // 0..23
    const int ty = threadIdx.y;              // 0..7
    const int tid = ty * 24 + tx;
    const int warp = tid >> 5;               // 0..5
    const int lane = tid & 31;
    const int f0 = tx * 4;
    const int nn0 = ty * 4;

    for (int i = tid; i < F1 * F1; i += 192) {
        int fo = i / F1, k = i % F1;
        swl[k * F1 + fo] = wl[i];
        swr[k * F1 + fo] = wr[i];
    }
    if (tid < F1) sb[tid] = bl[tid];

    const float4* x4 = (const float4*)x;
    const int ntiles = (n + L1_TN - 1) / L1_TN;
    for (int t = blockIdx.x; t < ntiles; t += gridDim.x) {
        const int base = t * L1_TN;
        __syncthreads();   // prev tile fully consumed (also covers weight load)

        // stage x tile (coalesced float4)
        for (int i = tid; i < L1_TN * 24; i += 192) {
            int node = i / 24, c = i % 24;
            int g = base + node;
            float4 v = make_float4(0.f, 0.f, 0.f, 0.f);
            if (g < n) v = x4[(size_t)g * 24 + c];
            ((float4*)sx)[node * 24 + c] = v;
        }

        // CSR-aggregate neighbor sums into sm (warp per node, register acc)
        for (int node = warp; node < L1_TN; node += 6) {
            int g = base + node;
            float4 acc = make_float4(0.f, 0.f, 0.f, 0.f);
            int deg = 0;
            if (g < n) {
                int s0 = g_off[g], s1 = g_off[g + 1];
                deg = s1 - s0;
                if (lane < 24) {
                    int i = s0;
                    for (; i + 1 < s1; i += 2) {
                        int sa = g_srcs[i], sb_ = g_srcs[i + 1];
                        float4 va = x4[(size_t)sa * 24 + lane];
                        float4 vb = x4[(size_t)sb_ * 24 + lane];
                        acc.x += va.x + vb.x; acc.y += va.y + vb.y;
                        acc.z += va.z + vb.z; acc.w += va.w + vb.w;
                    }
                    if (i < s1) {
                        float4 va = x4[(size_t)g_srcs[i] * 24 + lane];
                        acc.x += va.x; acc.y += va.y; acc.z += va.z; acc.w += va.w;
                    }
                }
            }
            if (lane < 24) ((float4*)sm)[node * 24 + lane] = acc;
            if (lane == 0) sinv[node] = 1.0f / fmaxf((float)deg, 1.0f);
        }
        __syncthreads();

        float l[4][4], r[4][4];
        #pragma unroll
        for (int a = 0; a < 4; a++)
            #pragma unroll
            for (int j = 0; j < 4; j++) { l[a][j] = 0.f; r[a][j] = 0.f; }

        const float4* sx4 = (const float4*)sx;
        const float4* sm4 = (const float4*)sm;
        const float4* swl4 = (const float4*)swl;
        const float4* swr4 = (const float4*)swr;
        for (int kk = 0; kk < 24; kk++) {
            float4 xv[4], mv[4];
            #pragma unroll
            for (int j = 0; j < 4; j++) {
                xv[j] = sx4[(nn0 + j) * 24 + kk];
                mv[j] = sm4[(nn0 + j) * 24 + kk];
            }
            #pragma unroll
            for (int i = 0; i < 4; i++) {
                int k = kk * 4 + i;
                float4 wa = swl4[k * 24 + tx];
                float4 wb = swr4[k * 24 + tx];
                #pragma unroll
                for (int j = 0; j < 4; j++) {
                    float xs = fcomp(xv[j], i);
                    float ms = fcomp(mv[j], i);
                    l[0][j] += wa.x * xs; l[1][j] += wa.y * xs;
                    l[2][j] += wa.z * xs; l[3][j] += wa.w * xs;
                    r[0][j] += wb.x * ms; r[1][j] += wb.y * ms;
                    r[2][j] += wb.z * ms; r[3][j] += wb.w * ms;
                }
            }
        }

        float b0 = sb[f0+0], b1 = sb[f0+1], b2 = sb[f0+2], b3 = sb[f0+3];
        #pragma unroll
        for (int j = 0; j < 4; j++) {
            int g = base + nn0 + j;
            if (g >= n) continue;
            float inv = sinv[nn0 + j];
            float4 o;
            o.x = l[0][j] + inv * r[0][j] + b0;
            o.y = l[1][j] + inv * r[1][j] + b1;
            o.z = l[2][j] + inv * r[2][j] + b2;
            o.w = l[3][j] + inv * r[3][j] + b3;
            o.x = o.x > 0.f ? o.x : (expf(o.x) - 1.0f);
            o.y = o.y > 0.f ? o.y : (expf(o.y) - 1.0f);
            o.z = o.z > 0.f ? o.z : (expf(o.z) - 1.0f);
            o.w = o.w > 0.f ? o.w : (expf(o.w) - 1.0f);
            ((float4*)g_h)[((size_t)g * F1 + f0) >> 2] = o;
        }
    }
}

// ---------------------------------------------------------------------------
// Layer 2 (fused dual GEMM): out = h @ w2_l^T + b2 ; y2 = h @ w2_r^T
// Block (16,16)=256 thr, 64 nodes/tile, 4 feat x 4 nodes per thread.
// ---------------------------------------------------------------------------
#define L2_TN 64
__global__ void layer2_kernel(const float* __restrict__ wl,
                              const float* __restrict__ bl,
                              const float* __restrict__ wr,
                              float* __restrict__ out,
                              int n) {
    extern __shared__ float smem[];
    float* swl = smem;                       // [96][64]
    float* swr = swl + F1 * F2;
    float* sh  = swr + F1 * F2;              // [64][96]
    float* sb  = sh  + L2_TN * F1;           // [64]

    const int tx = threadIdx.x;              // 0..15
    const int ty = threadIdx.y;              // 0..15
    const int tid = ty * 16 + tx;
    const int f0 = tx * 4;
    const int nn0 = ty * 4;

    for (int i = tid; i < F2 * F1; i += 256) {
        int fo = i / F1, k = i % F1;
        swl[k * F2 + fo] = wl[i];
        swr[k * F2 + fo] = wr[i];
    }
    if (tid < F2) sb[tid] = bl[tid];

    const int ntiles = (n + L2_TN - 1) / L2_TN;
    for (int t = blockIdx.x; t < ntiles; t += gridDim.x) {
        const int base = t * L2_TN;
        __syncthreads();

        for (int i = tid; i < L2_TN * 24; i += 256) {
            int node = i / 24, c = i % 24;
            int g = base + node;
            float4 v = make_float4(0.f, 0.f, 0.f, 0.f);
            if (g < n) v = ((const float4*)g_h)[(size_t)g * 24 + c];
            ((float4*)sh)[node * 24 + c] = v;
        }
        __syncthreads();

        float l[4][4], r[4][4];
        #pragma unroll
        for (int a = 0; a < 4; a++)
            #pragma unroll
            for (int j = 0; j < 4; j++) { l[a][j] = 0.f; r[a][j] = 0.f; }

        const float4* sh4 = (const float4*)sh;
        const float4* swl4 = (const float4*)swl;
        const float4* swr4 = (const float4*)swr;
        for (int kk = 0; kk < 24; kk++) {
            float4 hv[4];
            #pragma unroll
            for (int j = 0; j < 4; j++)
                hv[j] = sh4[(nn0 + j) * 24 + kk];
            #pragma unroll
            for (int i = 0; i < 4; i++) {
                int k = kk * 4 + i;
                float4 wa = swl4[k * 16 + tx];
                float4 wb = swr4[k * 16 + tx];
                #pragma unroll
                for (int j = 0; j < 4; j++) {
                    float hs = fcomp(hv[j], i);
                    l[0][j] += wa.x * hs; l[1][j] += wa.y * hs;
                    l[2][j] += wa.z * hs; l[3][j] += wa.w * hs;
                    r[0][j] += wb.x * hs; r[1][j] += wb.y * hs;
                    r[2][j] += wb.z * hs; r[3][j] += wb.w * hs;
                }
            }
        }

        float b0 = sb[f0+0], b1 = sb[f0+1], b2 = sb[f0+2], b3 = sb[f0+3];
        #pragma unroll
        for (int j = 0; j < 4; j++) {
            int g = base + nn0 + j;
            if (g >= n) continue;
            float4 o, y;
            o.x = l[0][j] + b0; y.x = r[0][j];
            o.y = l[1][j] + b1; y.y = r[1][j];
            o.z = l[2][j] + b2; y.z = r[2][j];
            o.w = l[3][j] + b3; y.w = r[3][j];
            ((float4*)out)[((size_t)g * F2 + f0) >> 2] = o;
            ((float4*)g_y2)[((size_t)g * F2 + f0) >> 2] = y;
        }
    }
}

// ---------------------------------------------------------------------------
// Layer-2 aggregation fused with final combine:
//   out[d] += mean_nbr(y2) ; half-warp (16 lanes) per dst, no atomics.
// ---------------------------------------------------------------------------
__global__ void agg2_kernel(float* __restrict__ out, int n) {
    int tid = blockIdx.x * blockDim.x + threadIdx.x;
    int d = tid >> 4;
    int lane = tid & 15;
    if (d >= n) return;
    int s0 = g_off[d], s1 = g_off[d + 1];
    const float4* y4 = (const float4*)g_y2;
    float4 acc = make_float4(0.f, 0.f, 0.f, 0.f);
    int i = s0;
    for (; i + 1 < s1; i += 2) {
        int sa = g_srcs[i], sb = g_srcs[i + 1];
        float4 va = y4[(size_t)sa * 16 + lane];
        float4 vb = y4[(size_t)sb * 16 + lane];
        acc.x += va.x + vb.x; acc.y += va.y + vb.y;
        acc.z += va.z + vb.z; acc.w += va.w + vb.w;
    }
    if (i < s1) {
        float4 va = y4[(size_t)g_srcs[i] * 16 + lane];
        acc.x += va.x; acc.y += va.y; acc.z += va.z; acc.w += va.w;
    }
    float inv = 1.0f / fmaxf((float)(s1 - s0), 1.0f);
    float4* o = (float4*)out + (size_t)d * 16 + lane;
    float4 ov = *o;
    ov.x += acc.x * inv; ov.y += acc.y * inv;
    ov.z += acc.z * inv; ov.w += acc.w * inv;
    *o = ov;
}

// ---------------------------------------------------------------------------
extern "C" void kernel_launch(void* const* d_in, const int* in_sizes, int n_in,
                              void* d_out, int out_size) {
    const float* x   = (const float*)d_in[0];
    const int*   ei  = (const int*)d_in[1];   // [2, E] int32
    const float* w1l = (const float*)d_in[2];
    const float* b1l = (const float*)d_in[3];
    const float* w1r = (const float*)d_in[4];
    const float* w2l = (const float*)d_in[5];
    const float* b2l = (const float*)d_in[6];
    const float* w2r = (const float*)d_in[7];
    float* out = (float*)d_out;

    const int n = in_sizes[0] / F1;
    const int e = in_sizes[1] / 2;
    const int* src = ei;
    const int* dst = ei + e;

    const int l1_smem = (2 * F1 * F1 + 2 * L1_TN * F1 + F1 + L1_TN) * (int)sizeof(float);
    const int l2_smem = (2 * F1 * F2 + L2_TN * F1 + F2) * (int)sizeof(float);
    cudaFuncSetAttribute(layer1_kernel, cudaFuncAttributeMaxDynamicSharedMemorySize, l1_smem);
    cudaFuncSetAttribute(layer2_kernel, cudaFuncAttributeMaxDynamicSharedMemorySize, l2_smem);

    // CSR build
    zero_deg_kernel<<<(n + 255) / 256, 256>>>(n);
    hist_kernel<<<(e + 255) / 256, 256>>>(dst, e);
    scan_kernel<<<1, SCAN_T>>>(n);
    scatter_kernel<<<(e + 255) / 256, 256>>>(src, dst, e);

    {   // layer 1 (fused aggregation + GEMM + ELU)
        int ntiles = (n + L1_TN - 1) / L1_TN;
        int grid = ntiles < 296 ? ntiles : 296;
        layer1_kernel<<<grid, dim3(24, 8), l1_smem>>>(x, w1l, b1l, w1r, n);
    }

    {   // layer 2 (dual GEMM)
        int ntiles = (n + L2_TN - 1) / L2_TN;
        int grid = ntiles < 296 ? ntiles : 296;
        layer2_kernel<<<grid, dim3(16, 16), l2_smem>>>(w2l, b2l, w2r, out, n);
    }

    {   // layer-2 aggregation + final combine
        long long threads = (long long)n * 16;
        int blocks = (int)((threads + 255) / 256);
        agg2_kernel<<<blocks, 256>>>(out, n);
    }
}

// round 6
// speedup vs baseline: 1.1106x; 1.1106x over previous
#include <cuda_runtime.h>
#include <math.h>

// Problem constants: N=50000, E=800000, F1=96, F2=64
#define MAXN 50000
#define MAXE 800000
#define F1 96
#define F2 64
#define SCAN_T 1024

// Scratch (device globals). __align__(16) for float4 access.
__device__ int g_deg[MAXN];
__device__ int g_off[MAXN + 1];
__device__ int g_cur[MAXN];
__device__ int g_srcs[MAXE];
__device__ __align__(16) float g_m1[MAXN * F1];   // mean of x over neighbors
__device__ __align__(16) float g_h [MAXN * F1];   // layer-1 output
__device__ __align__(16) float g_y2[MAXN * F2];   // h @ w2_r^T

__device__ __forceinline__ float fcomp(const float4& v, int i) {
    return i == 0 ? v.x : i == 1 ? v.y : i == 2 ? v.z : v.w;
}

// ---------------------------------------------------------------------------
// CSR build: zero degree -> histogram -> scan -> scatter
// ---------------------------------------------------------------------------
__global__ void zero_deg_kernel(int n) {
    int i = blockIdx.x * blockDim.x + threadIdx.x;
    if (i < n) g_deg[i] = 0;
}

__global__ void hist_kernel(const int* __restrict__ dst, int e) {
    int i = blockIdx.x * blockDim.x + threadIdx.x;
    if (i < e) atomicAdd(&g_deg[dst[i]], 1);
}

__global__ void scan_kernel(int n) {
    __shared__ int ssum[SCAN_T];
    int t = threadIdx.x;
    int chunk = (n + SCAN_T - 1) / SCAN_T;
    int start = t * chunk;
    int end = min(start + chunk, n);
    int local = 0;
    for (int i = start; i < end; i++) local += g_deg[i];
    ssum[t] = local;
    __syncthreads();
    for (int ofs = 1; ofs < SCAN_T; ofs <<= 1) {
        int v = (t >= ofs) ? ssum[t - ofs] : 0;
        __syncthreads();
        ssum[t] += v;
        __syncthreads();
    }
    int run = ssum[t] - local;   // exclusive prefix
    for (int i = start; i < end; i++) {
        g_off[i] = run;
        g_cur[i] = run;
        run += g_deg[i];
    }
    if (t == SCAN_T - 1) g_off[n] = ssum[SCAN_T - 1];
}

__global__ void scatter_kernel(const int* __restrict__ src,
                               const int* __restrict__ dst, int e) {
    int i = blockIdx.x * blockDim.x + threadIdx.x;
    if (i < e) {
        int d = dst[i];
        int p = atomicAdd(&g_cur[d], 1);
        g_srcs[p] = src[i];
    }
}

// ---------------------------------------------------------------------------
// agg1: g_m1[d] = mean_{s in N(d)} x[s].  One WARP per dst node.
// Lanes 0..23 each own one float4 chunk; neighbor loop unrolled x4 (MLP=4).
// ---------------------------------------------------------------------------
__global__ void agg1_kernel(const float4* __restrict__ x4, int n) {
    int w = (blockIdx.x * blockDim.x + threadIdx.x) >> 5;
    int lane = threadIdx.x & 31;
    if (w >= n || lane >= 24) return;
    int s0 = g_off[w], s1 = g_off[w + 1];
    float4 acc = make_float4(0.f, 0.f, 0.f, 0.f);
    int i = s0;
    for (; i + 3 < s1; i += 4) {
        int a = g_srcs[i], b = g_srcs[i+1], c = g_srcs[i+2], d = g_srcs[i+3];
        float4 va = x4[(size_t)a * 24 + lane];
        float4 vb = x4[(size_t)b * 24 + lane];
        float4 vc = x4[(size_t)c * 24 + lane];
        float4 vd = x4[(size_t)d * 24 + lane];
        acc.x += (va.x + vb.x) + (vc.x + vd.x);
        acc.y += (va.y + vb.y) + (vc.y + vd.y);
        acc.z += (va.z + vb.z) + (vc.z + vd.z);
        acc.w += (va.w + vb.w) + (vc.w + vd.w);
    }
    for (; i < s1; i++) {
        float4 va = x4[(size_t)g_srcs[i] * 24 + lane];
        acc.x += va.x; acc.y += va.y; acc.z += va.z; acc.w += va.w;
    }
    float inv = 1.0f / fmaxf((float)(s1 - s0), 1.0f);
    acc.x *= inv; acc.y *= inv; acc.z *= inv; acc.w *= inv;
    ((float4*)g_m1)[(size_t)w * 24 + lane] = acc;
}

// ---------------------------------------------------------------------------
// Layer 1 (dual GEMM + ELU): h = elu(x @ wl^T + b + m1 @ wr^T)
// Block (24,8)=192 thr, 32 nodes/tile, 4 feat x 4 nodes/thread, float4 LDS.
// ---------------------------------------------------------------------------
#define L1_TN 32
__global__ void layer1_kernel(const float* __restrict__ x,
                              const float* __restrict__ wl,
                              const float* __restrict__ bl,
                              const float* __restrict__ wr,
                              int n) {
    extern __shared__ float smem[];
    float* swl = smem;                       // [96][96]: swl[k*96+f]
    float* swr = swl + F1 * F1;
    float* sx  = swr + F1 * F1;              // [32][96] node-major
    float* sm  = sx  + L1_TN * F1;           // [32][96]
    float* sb  = sm  + L1_TN * F1;           // [96]

    const int tx = threadIdx.x;              // 0..23
    const int ty = threadIdx.y;              // 0..7
    const int tid = ty * 24 + tx;
    const int f0 = tx * 4;
    const int nn0 = ty * 4;

    for (int i = tid; i < F1 * F1; i += 192) {
        int fo = i / F1, k = i % F1;
        swl[k * F1 + fo] = wl[i];
        swr[k * F1 + fo] = wr[i];
    }
    if (tid < F1) sb[tid] = bl[tid];

    const float4* x4 = (const float4*)x;
    const float4* m4 = (const float4*)g_m1;
    const int ntiles = (n + L1_TN - 1) / L1_TN;
    for (int t = blockIdx.x; t < ntiles; t += gridDim.x) {
        const int base = t * L1_TN;
        __syncthreads();   // prev tile consumed (also covers weight load)

        for (int i = tid; i < L1_TN * 24; i += 192) {
            int node = i / 24, c = i % 24;
            int g = base + node;
            float4 vx = make_float4(0.f, 0.f, 0.f, 0.f);
            float4 vm = vx;
            if (g < n) {
                vx = x4[(size_t)g * 24 + c];
                vm = m4[(size_t)g * 24 + c];
            }
            ((float4*)sx)[node * 24 + c] = vx;
            ((float4*)sm)[node * 24 + c] = vm;
        }
        __syncthreads();

        float l[4][4], r[4][4];
        #pragma unroll
        for (int a = 0; a < 4; a++)
            #pragma unroll
            for (int j = 0; j < 4; j++) { l[a][j] = 0.f; r[a][j] = 0.f; }

        const float4* sx4 = (const float4*)sx;
        const float4* sm4 = (const float4*)sm;
        const float4* swl4 = (const float4*)swl;
        const float4* swr4 = (const float4*)swr;
        for (int kk = 0; kk < 24; kk++) {
            float4 xv[4], mv[4];
            #pragma unroll
            for (int j = 0; j < 4; j++) {
                xv[j] = sx4[(nn0 + j) * 24 + kk];
                mv[j] = sm4[(nn0 + j) * 24 + kk];
            }
            #pragma unroll
            for (int i = 0; i < 4; i++) {
                int k = kk * 4 + i;
                float4 wa = swl4[k * 24 + tx];
                float4 wb = swr4[k * 24 + tx];
                #pragma unroll
                for (int j = 0; j < 4; j++) {
                    float xs = fcomp(xv[j], i);
                    float ms = fcomp(mv[j], i);
                    l[0][j] += wa.x * xs; l[1][j] += wa.y * xs;
                    l[2][j] += wa.z * xs; l[3][j] += wa.w * xs;
                    r[0][j] += wb.x * ms; r[1][j] += wb.y * ms;
                    r[2][j] += wb.z * ms; r[3][j] += wb.w * ms;
                }
            }
        }

        float b0 = sb[f0+0], b1 = sb[f0+1], b2 = sb[f0+2], b3 = sb[f0+3];
        #pragma unroll
        for (int j = 0; j < 4; j++) {
            int g = base + nn0 + j;
            if (g >= n) continue;
            float4 o;
            o.x = l[0][j] + r[0][j] + b0;
            o.y = l[1][j] + r[1][j] + b1;
            o.z = l[2][j] + r[2][j] + b2;
            o.w = l[3][j] + r[3][j] + b3;
            o.x = o.x > 0.f ? o.x : (expf(o.x) - 1.0f);
            o.y = o.y > 0.f ? o.y : (expf(o.y) - 1.0f);
            o.z = o.z > 0.f ? o.z : (expf(o.z) - 1.0f);
            o.w = o.w > 0.f ? o.w : (expf(o.w) - 1.0f);
            ((float4*)g_h)[((size_t)g * F1 + f0) >> 2] = o;
        }
    }
}

// ---------------------------------------------------------------------------
// Layer 2 (fused dual GEMM): out = h @ w2_l^T + b2 ; y2 = h @ w2_r^T
// Block (16,16)=256 thr, 64 nodes/tile, 4 feat x 4 nodes/thread, float4 LDS.
// ---------------------------------------------------------------------------
#define L2_TN 64
__global__ void layer2_kernel(const float* __restrict__ wl,
                              const float* __restrict__ bl,
                              const float* __restrict__ wr,
                              float* __restrict__ out,
                              int n) {
    extern __shared__ float smem[];
    float* swl = smem;                       // [96][64]
    float* swr = swl + F1 * F2;
    float* sh  = swr + F1 * F2;              // [64][96]
    float* sb  = sh  + L2_TN * F1;           // [64]

    const int tx = threadIdx.x;              // 0..15
    const int ty = threadIdx.y;              // 0..15
    const int tid = ty * 16 + tx;
    const int f0 = tx * 4;
    const int nn0 = ty * 4;

    for (int i = tid; i < F2 * F1; i += 256) {
        int fo = i / F1, k = i % F1;
        swl[k * F2 + fo] = wl[i];
        swr[k * F2 + fo] = wr[i];
    }
    if (tid < F2) sb[tid] = bl[tid];

    const int ntiles = (n + L2_TN - 1) / L2_TN;
    for (int t = blockIdx.x; t < ntiles; t += gridDim.x) {
        const int base = t * L2_TN;
        __syncthreads();

        for (int i = tid; i < L2_TN * 24; i += 256) {
            int node = i / 24, c = i % 24;
            int g = base + node;
            float4 v = make_float4(0.f, 0.f, 0.f, 0.f);
            if (g < n) v = ((const float4*)g_h)[(size_t)g * 24 + c];
            ((float4*)sh)[node * 24 + c] = v;
        }
        __syncthreads();

        float l[4][4], r[4][4];
        #pragma unroll
        for (int a = 0; a < 4; a++)
            #pragma unroll
            for (int j = 0; j < 4; j++) { l[a][j] = 0.f; r[a][j] = 0.f; }

        const float4* sh4 = (const float4*)sh;
        const float4* swl4 = (const float4*)swl;
        const float4* swr4 = (const float4*)swr;
        for (int kk = 0; kk < 24; kk++) {
            float4 hv[4];
            #pragma unroll
            for (int j = 0; j < 4; j++)
                hv[j] = sh4[(nn0 + j) * 24 + kk];
            #pragma unroll
            for (int i = 0; i < 4; i++) {
                int k = kk * 4 + i;
                float4 wa = swl4[k * 16 + tx];
                float4 wb = swr4[k * 16 + tx];
                #pragma unroll
                for (int j = 0; j < 4; j++) {
                    float hs = fcomp(hv[j], i);
                    l[0][j] += wa.x * hs; l[1][j] += wa.y * hs;
                    l[2][j] += wa.z * hs; l[3][j] += wa.w * hs;
                    r[0][j] += wb.x * hs; r[1][j] += wb.y * hs;
                    r[2][j] += wb.z * hs; r[3][j] += wb.w * hs;
                }
            }
        }

        float b0 = sb[f0+0], b1 = sb[f0+1], b2 = sb[f0+2], b3 = sb[f0+3];
        #pragma unroll
        for (int j = 0; j < 4; j++) {
            int g = base + nn0 + j;
            if (g >= n) continue;
            float4 o, y;
            o.x = l[0][j] + b0; y.x = r[0][j];
            o.y = l[1][j] + b1; y.y = r[1][j];
            o.z = l[2][j] + b2; y.z = r[2][j];
            o.w = l[3][j] + b3; y.w = r[3][j];
            ((float4*)out)[((size_t)g * F2 + f0) >> 2] = o;
            ((float4*)g_y2)[((size_t)g * F2 + f0) >> 2] = y;
        }
    }
}

// ---------------------------------------------------------------------------
// agg2 + final: out[d] += mean_nbr(y2). Half-warp per dst, unroll x4, no atomics.
// ---------------------------------------------------------------------------
__global__ void agg2_kernel(float* __restrict__ out, int n) {
    int tid = blockIdx.x * blockDim.x + threadIdx.x;
    int d = tid >> 4;
    int lane = tid & 15;
    if (d >= n) return;
    int s0 = g_off[d], s1 = g_off[d + 1];
    const float4* y4 = (const float4*)g_y2;
    float4 acc = make_float4(0.f, 0.f, 0.f, 0.f);
    int i = s0;
    for (; i + 3 < s1; i += 4) {
        int a = g_srcs[i], b = g_srcs[i+1], c = g_srcs[i+2], dd = g_srcs[i+3];
        float4 va = y4[(size_t)a * 16 + lane];
        float4 vb = y4[(size_t)b * 16 + lane];
        float4 vc = y4[(size_t)c * 16 + lane];
        float4 vd = y4[(size_t)dd * 16 + lane];
        acc.x += (va.x + vb.x) + (vc.x + vd.x);
        acc.y += (va.y + vb.y) + (vc.y + vd.y);
        acc.z += (va.z + vb.z) + (vc.z + vd.z);
        acc.w += (va.w + vb.w) + (vc.w + vd.w);
    }
    for (; i < s1; i++) {
        float4 va = y4[(size_t)g_srcs[i] * 16 + lane];
        acc.x += va.x; acc.y += va.y; acc.z += va.z; acc.w += va.w;
    }
    float inv = 1.0f / fmaxf((float)(s1 - s0), 1.0f);
    float4* o = (float4*)out + (size_t)d * 16 + lane;
    float4 ov = *o;
    ov.x += acc.x * inv; ov.y += acc.y * inv;
    ov.z += acc.z * inv; ov.w += acc.w * inv;
    *o = ov;
}

// ---------------------------------------------------------------------------
extern "C" void kernel_launch(void* const* d_in, const int* in_sizes, int n_in,
                              void* d_out, int out_size) {
    const float* x   = (const float*)d_in[0];
    const int*   ei  = (const int*)d_in[1];   // [2, E] int32
    const float* w1l = (const float*)d_in[2];
    const float* b1l = (const float*)d_in[3];
    const float* w1r = (const float*)d_in[4];
    const float* w2l = (const float*)d_in[5];
    const float* b2l = (const float*)d_in[6];
    const float* w2r = (const float*)d_in[7];
    float* out = (float*)d_out;

    const int n = in_sizes[0] / F1;
    const int e = in_sizes[1] / 2;
    const int* src = ei;
    const int* dst = ei + e;

    const int l1_smem = (2 * F1 * F1 + 2 * L1_TN * F1 + F1) * (int)sizeof(float);
    const int l2_smem = (2 * F1 * F2 + L2_TN * F1 + F2) * (int)sizeof(float);
    cudaFuncSetAttribute(layer1_kernel, cudaFuncAttributeMaxDynamicSharedMemorySize, l1_smem);
    cudaFuncSetAttribute(layer2_kernel, cudaFuncAttributeMaxDynamicSharedMemorySize, l2_smem);

    // CSR build
    zero_deg_kernel<<<(n + 255) / 256, 256>>>(n);
    hist_kernel<<<(e + 255) / 256, 256>>>(dst, e);
    scan_kernel<<<1, SCAN_T>>>(n);
    scatter_kernel<<<(e + 255) / 256, 256>>>(src, dst, e);

    // layer-1 aggregation: one warp per dst node
    agg1_kernel<<<(n * 32 + 255) / 256, 256>>>((const float4*)x, n);

    {   // layer 1 dual GEMM + ELU
        int ntiles = (n + L1_TN - 1) / L1_TN;
        int grid = ntiles < 296 ? ntiles : 296;
        layer1_kernel<<<grid, dim3(24, 8), l1_smem>>>(x, w1l, b1l, w1r, n);
    }

    {   // layer 2 dual GEMM
        int ntiles = (n + L2_TN - 1) / L2_TN;
        int grid = ntiles < 444 ? ntiles : 444;
        layer2_kernel<<<grid, dim3(16, 16), l2_smem>>>(w2l, b2l, w2r, out, n);
    }

    {   // layer-2 aggregation + final combine
        long long threads = (long long)n * 16;
        int blocks = (int)((threads + 255) / 256);
        agg2_kernel<<<blocks, 256>>>(out, n);
    }
}

// round 7
// speedup vs baseline: 1.4017x; 1.2621x over previous
#include <cuda_runtime.h>
#include <math.h>
#include <stdint.h>

// Problem constants: N=50000, E=800000, F1=96, F2=64
#define MAXN 50000
#define MAXE 800000
#define F1 96
#define F2 64
#define SCAN_T 1024

// Scratch (device globals). __align__(16) for float4 access.
__device__ int g_deg[MAXN];
__device__ int g_off[MAXN + 1];
__device__ int g_cur[MAXN];
__device__ int g_srcs[MAXE];
__device__ __align__(16) float g_m1[MAXN * F1];   // mean of x over neighbors
__device__ __align__(16) float g_h [MAXN * F1];   // layer-1 output
__device__ __align__(16) float g_y2[MAXN * F2];   // h @ w2_r^T

// ---------------------------------------------------------------------------
// tf32 helpers
// ---------------------------------------------------------------------------
__device__ __forceinline__ uint32_t cvt_tf32(float f) {
    uint32_t u;
    asm("cvt.rna.tf32.f32 %0, %1;" : "=r"(u) : "f"(f));
    return u;
}

__device__ __forceinline__ void mma_tf32(float* c,
                                         uint32_t a0, uint32_t a1,
                                         uint32_t a2, uint32_t a3,
                                         uint32_t b0, uint32_t b1) {
    asm volatile(
        "mma.sync.aligned.m16n8k8.row.col.f32.tf32.tf32.f32 "
        "{%0,%1,%2,%3}, {%4,%5,%6,%7}, {%8,%9}, {%0,%1,%2,%3};"
        : "+f"(c[0]), "+f"(c[1]), "+f"(c[2]), "+f"(c[3])
        : "r"(a0), "r"(a1), "r"(a2), "r"(a3), "r"(b0), "r"(b1));
}

__device__ __forceinline__ float elu1(float v) {
    return v > 0.f ? v : (expf(v) - 1.0f);
}

// ---------------------------------------------------------------------------
// CSR build: zero degree -> histogram -> scan -> scatter
// ---------------------------------------------------------------------------
__global__ void zero_deg_kernel(int n) {
    int i = blockIdx.x * blockDim.x + threadIdx.x;
    if (i < n) g_deg[i] = 0;
}

__global__ void hist_kernel(const int* __restrict__ dst, int e) {
    int i = blockIdx.x * blockDim.x + threadIdx.x;
    if (i < e) atomicAdd(&g_deg[dst[i]], 1);
}

__global__ void scan_kernel(int n) {
    __shared__ int ssum[SCAN_T];
    int t = threadIdx.x;
    int chunk = (n + SCAN_T - 1) / SCAN_T;
    int start = t * chunk;
    int end = min(start + chunk, n);
    int local = 0;
    for (int i = start; i < end; i++) local += g_deg[i];
    ssum[t] = local;
    __syncthreads();
    for (int ofs = 1; ofs < SCAN_T; ofs <<= 1) {
        int v = (t >= ofs) ? ssum[t - ofs] : 0;
        __syncthreads();
        ssum[t] += v;
        __syncthreads();
    }
    int run = ssum[t] - local;   // exclusive prefix
    for (int i = start; i < end; i++) {
        g_off[i] = run;
        g_cur[i] = run;
        run += g_deg[i];
    }
    if (t == SCAN_T - 1) g_off[n] = ssum[SCAN_T - 1];
}

__global__ void scatter_kernel(const int* __restrict__ src,
                               const int* __restrict__ dst, int e) {
    int i = blockIdx.x * blockDim.x + threadIdx.x;
    if (i < e) {
        int d = dst[i];
        int p = atomicAdd(&g_cur[d], 1);
        g_srcs[p] = src[i];
    }
}

// ---------------------------------------------------------------------------
// agg1: g_m1[d] = mean_{s in N(d)} x[s].  One WARP per dst node.
// Lanes 0..23 each own one float4 chunk; neighbor loop unrolled x4.
// ---------------------------------------------------------------------------
__global__ void agg1_kernel(const float4* __restrict__ x4, int n) {
    int w = (blockIdx.x * blockDim.x + threadIdx.x) >> 5;
    int lane = threadIdx.x & 31;
    if (w >= n || lane >= 24) return;
    int s0 = g_off[w], s1 = g_off[w + 1];
    float4 acc = make_float4(0.f, 0.f, 0.f, 0.f);
    int i = s0;
    for (; i + 3 < s1; i += 4) {
        int a = g_srcs[i], b = g_srcs[i+1], c = g_srcs[i+2], d = g_srcs[i+3];
        float4 va = x4[(size_t)a * 24 + lane];
        float4 vb = x4[(size_t)b * 24 + lane];
        float4 vc = x4[(size_t)c * 24 + lane];
        float4 vd = x4[(size_t)d * 24 + lane];
        acc.x += (va.x + vb.x) + (vc.x + vd.x);
        acc.y += (va.y + vb.y) + (vc.y + vd.y);
        acc.z += (va.z + vb.z) + (vc.z + vd.z);
        acc.w += (va.w + vb.w) + (vc.w + vd.w);
    }
    for (; i < s1; i++) {
        float4 va = x4[(size_t)g_srcs[i] * 24 + lane];
        acc.x += va.x; acc.y += va.y; acc.z += va.z; acc.w += va.w;
    }
    float inv = 1.0f / fmaxf((float)(s1 - s0), 1.0f);
    acc.x *= inv; acc.y *= inv; acc.z *= inv; acc.w *= inv;
    ((float4*)g_m1)[(size_t)w * 24 + lane] = acc;
}

// ---------------------------------------------------------------------------
// Layer 1 (tf32 tensor-core GEMM + ELU):
//   h = elu([x | m1] @ [w1_l | w1_r]^T + b1)   -- M x 192 x 96
// Block: 256 thr (8 warps), 128 nodes/tile, warp computes 16 nodes x 96.
// SMEM: A 128x196 (stride%32==4 -> conflict-free A frags),
//       B 192x104 (stride%32==8 -> conflict-free B frags), bias 96.
// ---------------------------------------------------------------------------
#define L1_AS 196
#define L1_BS 104
__global__ __launch_bounds__(256, 1)
void layer1_tc(const float* __restrict__ x,
               const float* __restrict__ wl,
               const float* __restrict__ bl,
               const float* __restrict__ wr,
               int n) {
    extern __shared__ uint32_t smem1[];
    uint32_t* sA = smem1;                        // [128][196] tf32
    uint32_t* sB = sA + 128 * L1_AS;             // [192][104] tf32
    float* sbias = (float*)(sB + 192 * L1_BS);   // [96]

    const int tid = threadIdx.x;
    const int warp = tid >> 5;
    const int lane = tid & 31;
    const int gid = lane >> 2;     // group id 0..7
    const int tig = lane & 3;      // thread in group 0..3
    const int base = blockIdx.x * 128;

    // stage B: sB[k][f] = wl[f][k] (k<96), wr[f][k-96] (k>=96)
    for (int i = tid; i < F1 * F1; i += 256) {
        int f = i / F1, k = i % F1;
        sB[k * L1_BS + f] = cvt_tf32(wl[i]);
        sB[(k + F1) * L1_BS + f] = cvt_tf32(wr[i]);
    }
    if (tid < F1) sbias[tid] = bl[tid];

    // stage A: rows=nodes, cols 0..95 = x, 96..191 = m1 (zero-pad rows >= n)
    const float4* x4 = (const float4*)x;
    const float4* m4 = (const float4*)g_m1;
    for (int i = tid; i < 128 * 24; i += 256) {
        int r = i / 24, c = i % 24;
        int g = base + r;
        float4 vx = make_float4(0.f, 0.f, 0.f, 0.f);
        float4 vm = vx;
        if (g < n) { vx = x4[(size_t)g * 24 + c]; vm = m4[(size_t)g * 24 + c]; }
        uint32_t* pa = &sA[r * L1_AS + c * 4];
        pa[0] = cvt_tf32(vx.x); pa[1] = cvt_tf32(vx.y);
        pa[2] = cvt_tf32(vx.z); pa[3] = cvt_tf32(vx.w);
        uint32_t* pm = &sA[r * L1_AS + F1 + c * 4];
        pm[0] = cvt_tf32(vm.x); pm[1] = cvt_tf32(vm.y);
        pm[2] = cvt_tf32(vm.z); pm[3] = cvt_tf32(vm.w);
    }
    __syncthreads();

    float c[12][4];
    #pragma unroll
    for (int nt = 0; nt < 12; nt++)
        #pragma unroll
        for (int q = 0; q < 4; q++) c[nt][q] = 0.f;

    const int row0 = warp * 16 + gid;
    #pragma unroll 2
    for (int kb = 0; kb < 24; kb++) {
        int k0 = kb * 8;
        uint32_t a0 = sA[row0 * L1_AS + k0 + tig];
        uint32_t a1 = sA[(row0 + 8) * L1_AS + k0 + tig];
        uint32_t a2 = sA[row0 * L1_AS + k0 + tig + 4];
        uint32_t a3 = sA[(row0 + 8) * L1_AS + k0 + tig + 4];
        #pragma unroll
        for (int nt = 0; nt < 12; nt++) {
            uint32_t b0 = sB[(k0 + tig) * L1_BS + nt * 8 + gid];
            uint32_t b1 = sB[(k0 + tig + 4) * L1_BS + nt * 8 + gid];
            mma_tf32(c[nt], a0, a1, a2, a3, b0, b1);
        }
    }

    // epilogue: bias + ELU, scalar stores
    int r0 = base + row0, r1 = r0 + 8;
    #pragma unroll
    for (int nt = 0; nt < 12; nt++) {
        int col = nt * 8 + tig * 2;
        float bi0 = sbias[col], bi1 = sbias[col + 1];
        if (r0 < n) {
            g_h[(size_t)r0 * F1 + col]     = elu1(c[nt][0] + bi0);
            g_h[(size_t)r0 * F1 + col + 1] = elu1(c[nt][1] + bi1);
        }
        if (r1 < n) {
            g_h[(size_t)r1 * F1 + col]     = elu1(c[nt][2] + bi0);
            g_h[(size_t)r1 * F1 + col + 1] = elu1(c[nt][3] + bi1);
        }
    }
}

// ---------------------------------------------------------------------------
// Layer 2 (tf32 tensor-core GEMM, fused dual output):
//   [out_partial | y2] = h @ [w2_l^T | w2_r^T]   -- M x 96 x 128
// Block: 256 thr, 128 nodes/tile; cols 0..63 -> out (+bias), 64..127 -> y2.
// SMEM: A 128x100, B 96x136, bias 64.  (2 blocks/SM)
// ---------------------------------------------------------------------------
#define L2_AS 100
#define L2_BS 136
__global__ __launch_bounds__(256, 2)
void layer2_tc(const float* __restrict__ wl,
               const float* __restrict__ bl,
               const float* __restrict__ wr,
               float* __restrict__ out,
               int n) {
    extern __shared__ uint32_t smem2[];
    uint32_t* sA = smem2;                        // [128][100]
    uint32_t* sB = sA + 128 * L2_AS;             // [96][136]
    float* sbias = (float*)(sB + F1 * L2_BS);    // [64]

    const int tid = threadIdx.x;
    const int warp = tid >> 5;
    const int lane = tid & 31;
    const int gid = lane >> 2;
    const int tig = lane & 3;
    const int base = blockIdx.x * 128;

    // stage B: sB[k][f] = w2l[f][k] (f<64), sB[k][64+f] = w2r[f][k]
    for (int i = tid; i < F2 * F1; i += 256) {
        int f = i / F1, k = i % F1;
        sB[k * L2_BS + f] = cvt_tf32(wl[i]);
        sB[k * L2_BS + F2 + f] = cvt_tf32(wr[i]);
    }
    if (tid < F2) sbias[tid] = bl[tid];

    // stage A: h rows (zero-pad)
    const float4* h4 = (const float4*)g_h;
    for (int i = tid; i < 128 * 24; i += 256) {
        int r = i / 24, c = i % 24;
        int g = base + r;
        float4 v = make_float4(0.f, 0.f, 0.f, 0.f);
        if (g < n) v = h4[(size_t)g * 24 + c];
        uint32_t* pa = &sA[r * L2_AS + c * 4];
        pa[0] = cvt_tf32(v.x); pa[1] = cvt_tf32(v.y);
        pa[2] = cvt_tf32(v.z); pa[3] = cvt_tf32(v.w);
    }
    __syncthreads();

    float c[16][4];
    #pragma unroll
    for (int nt = 0; nt < 16; nt++)
        #pragma unroll
        for (int q = 0; q < 4; q++) c[nt][q] = 0.f;

    const int row0 = warp * 16 + gid;
    #pragma unroll 2
    for (int kb = 0; kb < 12; kb++) {
        int k0 = kb * 8;
        uint32_t a0 = sA[row0 * L2_AS + k0 + tig];
        uint32_t a1 = sA[(row0 + 8) * L2_AS + k0 + tig];
        uint32_t a2 = sA[row0 * L2_AS + k0 + tig + 4];
        uint32_t a3 = sA[(row0 + 8) * L2_AS + k0 + tig + 4];
        #pragma unroll
        for (int nt = 0; nt < 16; nt++) {
            uint32_t b0 = sB[(k0 + tig) * L2_BS + nt * 8 + gid];
            uint32_t b1 = sB[(k0 + tig + 4) * L2_BS + nt * 8 + gid];
            mma_tf32(c[nt], a0, a1, a2, a3, b0, b1);
        }
    }

    int r0 = base + row0, r1 = r0 + 8;
    #pragma unroll
    for (int nt = 0; nt < 16; nt++) {
        int col = nt * 8 + tig * 2;
        if (col < F2) {   // -> out with bias
            float bi0 = sbias[col], bi1 = sbias[col + 1];
            if (r0 < n) {
                out[(size_t)r0 * F2 + col]     = c[nt][0] + bi0;
                out[(size_t)r0 * F2 + col + 1] = c[nt][1] + bi1;
            }
            if (r1 < n) {
                out[(size_t)r1 * F2 + col]     = c[nt][2] + bi0;
                out[(size_t)r1 * F2 + col + 1] = c[nt][3] + bi1;
            }
        } else {          // -> y2
            int cy = col - F2;
            if (r0 < n) {
                g_y2[(size_t)r0 * F2 + cy]     = c[nt][0];
                g_y2[(size_t)r0 * F2 + cy + 1] = c[nt][1];
            }
            if (r1 < n) {
                g_y2[(size_t)r1 * F2 + cy]     = c[nt][2];
                g_y2[(size_t)r1 * F2 + cy + 1] = c[nt][3];
            }
        }
    }
}

// ---------------------------------------------------------------------------
// agg2 + final: out[d] += mean_nbr(y2). Half-warp per dst, unroll x4.
// ---------------------------------------------------------------------------
__global__ void agg2_kernel(float* __restrict__ out, int n) {
    int tid = blockIdx.x * blockDim.x + threadIdx.x;
    int d = tid >> 4;
    int lane = tid & 15;
    if (d >= n) return;
    int s0 = g_off[d], s1 = g_off[d + 1];
    const float4* y4 = (const float4*)g_y2;
    float4 acc = make_float4(0.f, 0.f, 0.f, 0.f);
    int i = s0;
    for (; i + 3 < s1; i += 4) {
        int a = g_srcs[i], b = g_srcs[i+1], c = g_srcs[i+2], dd = g_srcs[i+3];
        float4 va = y4[(size_t)a * 16 + lane];
        float4 vb = y4[(size_t)b * 16 + lane];
        float4 vc = y4[(size_t)c * 16 + lane];
        float4 vd = y4[(size_t)dd * 16 + lane];
        acc.x += (va.x + vb.x) + (vc.x + vd.x);
        acc.y += (va.y + vb.y) + (vc.y + vd.y);
        acc.z += (va.z + vb.z) + (vc.z + vd.z);
        acc.w += (va.w + vb.w) + (vc.w + vd.w);
    }
    for (; i < s1; i++) {
        float4 va = y4[(size_t)g_srcs[i] * 16 + lane];
        acc.x += va.x; acc.y += va.y; acc.z += va.z; acc.w += va.w;
    }
    float inv = 1.0f / fmaxf((float)(s1 - s0), 1.0f);
    float4* o = (float4*)out + (size_t)d * 16 + lane;
    float4 ov = *o;
    ov.x += acc.x * inv; ov.y += acc.y * inv;
    ov.z += acc.z * inv; ov.w += acc.w * inv;
    *o = ov;
}

// ---------------------------------------------------------------------------
extern "C" void kernel_launch(void* const* d_in, const int* in_sizes, int n_in,
                              void* d_out, int out_size) {
    const float* x   = (const float*)d_in[0];
    const int*   ei  = (const int*)d_in[1];   // [2, E] int32
    const float* w1l = (const float*)d_in[2];
    const float* b1l = (const float*)d_in[3];
    const float* w1r = (const float*)d_in[4];
    const float* w2l = (const float*)d_in[5];
    const float* b2l = (const float*)d_in[6];
    const float* w2r = (const float*)d_in[7];
    float* out = (float*)d_out;

    const int n = in_sizes[0] / F1;
    const int e = in_sizes[1] / 2;
    const int* src = ei;
    const int* dst = ei + e;

    const int l1_smem = (128 * L1_AS + 192 * L1_BS) * 4 + F1 * 4;   // ~180.6 KB
    const int l2_smem = (128 * L2_AS + F1 * L2_BS) * 4 + F2 * 4;    // ~103.7 KB
    cudaFuncSetAttribute(layer1_tc, cudaFuncAttributeMaxDynamicSharedMemorySize, l1_smem);
    cudaFuncSetAttribute(layer2_tc, cudaFuncAttributeMaxDynamicSharedMemorySize, l2_smem);

    // CSR build
    zero_deg_kernel<<<(n + 255) / 256, 256>>>(n);
    hist_kernel<<<(e + 255) / 256, 256>>>(dst, e);
    scan_kernel<<<1, SCAN_T>>>(n);
    scatter_kernel<<<(e + 255) / 256, 256>>>(src, dst, e);

    // layer-1 aggregation: one warp per dst node
    agg1_kernel<<<(n * 32 + 255) / 256, 256>>>((const float4*)x, n);

    // layer 1: tf32 tensor-core GEMM + ELU
    int blocks1 = (n + 127) / 128;
    layer1_tc<<<blocks1, 256, l1_smem>>>(x, w1l, b1l, w1r, n);

    // layer 2: tf32 tensor-core GEMM (dual output)
    int blocks2 = (n + 127) / 128;
    layer2_tc<<<blocks2, 256, l2_smem>>>(w2l, b2l, w2r, out, n);

    // layer-2 aggregation + final combine
    long long threads = (long long)n * 16;
    int blocksA = (int)((threads + 255) / 256);
    agg2_kernel<<<blocksA, 256>>>(out, n);
}